// round 8
// baseline (speedup 1.0000x reference)
#include <cuda_runtime.h>
#include <cuda_fp16.h>
#include <cstdint>

// ---------------------------------------------------------------------------
// Model constants
// ---------------------------------------------------------------------------
#define BATCH     8
#define SEQ       512
#define INPUT_DIM 32
#define DMODEL    256
#define NLAYERS   4
#define DSTATE    16
#define DCONV     4
#define DINNER    512
#define DTRANK    16
#define MROWS     (BATCH*SEQ)    // 4096
#define LN_EPS    1e-5f

// ---------------------------------------------------------------------------
// Device scratch
// ---------------------------------------------------------------------------
__device__ float  g_h   [MROWS * DMODEL];
__device__ __half g_xnh [MROWS * DMODEL];
__device__ float  g_xz  [MROWS * 2 * DINNER];
__device__ float  g_u   [MROWS * DINNER];
__device__ __half g_uh  [MROWS * DINNER];
__device__ float  g_dbl [MROWS * 48];
__device__ __half g_yh  [MROWS * DINNER];
__device__ float  g_t1  [BATCH * DMODEL];
__device__ float  g_part[2 * MROWS * DMODEL];     // split-K partials

// half scratch for converted inputs/weights (offsets in halves)
#define X_H    0          // x:            4096*32   = 131072
#define IPW_H  131072     // input_proj_w: 256*32    = 8192
#define INW_H  139264     // in_proj_w:    4*1024*256= 1048576 (l*262144)
#define XPW_H  1187840    // x_proj_w:     4*48*512  = 98304   (l*24576)
#define OPW_H  1286144    // out_proj_w:   4*256*512 = 524288  (l*131072)
#define WH_TOTAL 1810432
__device__ __half g_wh[WH_TOTAL];

// ---------------------------------------------------------------------------
// PTX helpers
// ---------------------------------------------------------------------------
__device__ __forceinline__ void mma_f16(float* cc, const uint32_t* a, const uint32_t* b) {
    asm volatile("mma.sync.aligned.m16n8k16.row.col.f32.f16.f16.f32 "
                 "{%0,%1,%2,%3}, {%4,%5,%6,%7}, {%8,%9}, {%0,%1,%2,%3};"
                 : "+f"(cc[0]), "+f"(cc[1]), "+f"(cc[2]), "+f"(cc[3])
                 : "r"(a[0]), "r"(a[1]), "r"(a[2]), "r"(a[3]),
                   "r"(b[0]), "r"(b[1]));
}

__device__ __forceinline__ uint32_t smem_u32(const void* p) {
    uint32_t a;
    asm("{ .reg .u64 t; cvta.to.shared.u64 t, %1; cvt.u32.u64 %0, t; }"
        : "=r"(a) : "l"(p));
    return a;
}

__device__ __forceinline__ void cpasync16(uint32_t dst, const void* src, int src_sz) {
    asm volatile("cp.async.cg.shared.global [%0], [%1], 16, %2;"
                 :: "r"(dst), "l"(src), "r"(src_sz) : "memory");
}
#define CP_COMMIT()  asm volatile("cp.async.commit_group;" ::: "memory")
#define CP_WAIT(n)   asm volatile("cp.async.wait_group %0;" :: "n"(n) : "memory")

// ---------------------------------------------------------------------------
// fp16 mma.sync NT GEMM, cp.async double buffer (static 24KB SMEM).
//   C[m,n] = sum_k A[m,k] * W[n,k]   (+bias)   fp32 accumulate/output
// CTA 128x128, BK=16 (one m16n8k16 step/tile), 256 threads, warp tile 32x64.
// Stage: A/B 128 rows x 24 halves (48B row -> conflict-free frag loads).
// Split-K via blockIdx.z (k-slice z*Klen.., C += z*zstride).
// Requirements: M%128==0, Klen%16==0, N%2==0 or guarded, lda/ldw %8==0.
// ---------------------------------------------------------------------------
#define BM 128
#define BN 128
#define BK 16
#define SLDH 24
#define STAGE_H (BM * SLDH)    // 3072 halves

__global__ __launch_bounds__(256)
void gemm_h(const __half* __restrict__ A, int lda,
            const __half* __restrict__ W, int ldw,
            const float* __restrict__ bias,
            float* __restrict__ C, int ldc, size_t zstride,
            int N, int Klen)
{
    __shared__ __half Asm[2][STAGE_H];
    __shared__ __half Bsm[2][STAGE_H];

    const int tid  = threadIdx.x;
    const int wid  = tid >> 5;
    const int lane = tid & 31;
    const int wm   = wid & 3;
    const int wn   = wid >> 2;
    const int g    = lane >> 2;
    const int c    = lane & 3;
    const int m0   = wm * 32;
    const int n0   = wn * 64;

    const int row0 = blockIdx.y * BM;
    const int col0 = blockIdx.x * BN;
    const int kofs = blockIdx.z * Klen;
    C += (size_t)blockIdx.z * zstride;

    // cp.async mapping: 256 threads = 128 rows x 2 chunks of 16B (8 halves)
    const int cr = tid >> 1;
    const int ck = (tid & 1) * 8;
    const int bvalid = (col0 + cr) < N ? 16 : 0;

    const uint32_t smA = smem_u32(Asm);
    const uint32_t smB = smem_u32(Bsm);
    const int T = Klen / BK;

    auto issue = [&](int t) {
        if (t < T) {
            const __half* Ap = A + (size_t)(row0 + cr) * lda + kofs + t * BK + ck;
            cpasync16(smA + ((t & 1) * STAGE_H + cr * SLDH + ck) * 2, Ap, 16);
            const __half* Wp = W + (size_t)(col0 + cr) * ldw + kofs + t * BK + ck;
            cpasync16(smB + ((t & 1) * STAGE_H + cr * SLDH + ck) * 2, Wp, bvalid);
        }
    };

    issue(0); CP_COMMIT();

    float acc[2][8][4];
#pragma unroll
    for (int mi = 0; mi < 2; mi++)
#pragma unroll
        for (int ni = 0; ni < 8; ni++)
#pragma unroll
            for (int e = 0; e < 4; e++) acc[mi][ni][e] = 0.f;

    for (int t = 0; t < T; t++) {
        issue(t + 1);
        CP_COMMIT();
        CP_WAIT(1);
        __syncthreads();

        const __half* As = Asm[t & 1];
        const __half* Bs = Bsm[t & 1];

        uint32_t a[2][4], b[8][2];
#pragma unroll
        for (int mi = 0; mi < 2; mi++) {
            const int r = m0 + mi * 16 + g;
            a[mi][0] = *(const uint32_t*)&As[(r    ) * SLDH + 2 * c];
            a[mi][1] = *(const uint32_t*)&As[(r + 8) * SLDH + 2 * c];
            a[mi][2] = *(const uint32_t*)&As[(r    ) * SLDH + 2 * c + 8];
            a[mi][3] = *(const uint32_t*)&As[(r + 8) * SLDH + 2 * c + 8];
        }
#pragma unroll
        for (int ni = 0; ni < 8; ni++) {
            const int r = n0 + ni * 8 + g;
            b[ni][0] = *(const uint32_t*)&Bs[r * SLDH + 2 * c];
            b[ni][1] = *(const uint32_t*)&Bs[r * SLDH + 2 * c + 8];
        }
#pragma unroll
        for (int mi = 0; mi < 2; mi++)
#pragma unroll
            for (int ni = 0; ni < 8; ni++)
                mma_f16(acc[mi][ni], a[mi], b[ni]);

        __syncthreads();
    }

    // ---- epilogue ----
#pragma unroll
    for (int mi = 0; mi < 2; mi++) {
#pragma unroll
        for (int ni = 0; ni < 8; ni++) {
            const int colb = col0 + n0 + ni * 8;
            if (colb < N) {
                const int cc = colb + c * 2;
#pragma unroll
                for (int half = 0; half < 2; half++) {
                    const int r = row0 + m0 + mi * 16 + g + half * 8;
                    float2 v = make_float2(acc[mi][ni][half * 2],
                                           acc[mi][ni][half * 2 + 1]);
                    if (bias) { v.x += bias[cc]; v.y += bias[cc + 1]; }
                    *(float2*)(C + (size_t)r * ldc + cc) = v;
                }
            }
        }
    }
}

// ---------------------------------------------------------------------------
// fp32 -> fp16 conversion (n % 8 == 0)
// ---------------------------------------------------------------------------
__global__ __launch_bounds__(256)
void cvt_kernel(const float* __restrict__ src, __half* __restrict__ dst, int n)
{
    int i = blockIdx.x * blockDim.x + threadIdx.x;
    if (i * 8 >= n) return;
    const float4* s4 = (const float4*)src;
    float4 v0 = s4[i * 2], v1 = s4[i * 2 + 1];
    __half2* d2 = (__half2*)dst;
    d2[i * 4 + 0] = __floats2half2_rn(v0.x, v0.y);
    d2[i * 4 + 1] = __floats2half2_rn(v0.z, v0.w);
    d2[i * 4 + 2] = __floats2half2_rn(v1.x, v1.y);
    d2[i * 4 + 3] = __floats2half2_rn(v1.z, v1.w);
}

// ---------------------------------------------------------------------------
// Split-K reduce: out[i] = (resid?resid[i]:0) + sum_z part[z*zstride + i]
// ---------------------------------------------------------------------------
__global__ __launch_bounds__(256)
void reduce_kernel(const float* __restrict__ part, size_t zstride, int nz,
                   const float* __restrict__ resid,
                   float* __restrict__ out, int n)
{
    int i = (blockIdx.x * blockDim.x + threadIdx.x) * 4;
    if (i >= n) return;
    float4 s = resid ? *(const float4*)(resid + i) : make_float4(0.f,0.f,0.f,0.f);
    for (int zi = 0; zi < nz; zi++) {
        float4 p = *(const float4*)(part + (size_t)zi * zstride + i);
        s.x += p.x; s.y += p.y; s.z += p.z; s.w += p.w;
    }
    *(float4*)(out + i) = s;
}

// ---------------------------------------------------------------------------
// LayerNorm: one warp per row of 256; writes fp16
// ---------------------------------------------------------------------------
__global__ __launch_bounds__(256)
void ln_kernel(const float* __restrict__ h,
               const float* __restrict__ w, const float* __restrict__ b,
               __half* __restrict__ out)
{
    int row  = blockIdx.x * 8 + (threadIdx.x >> 5);
    int lane = threadIdx.x & 31;
    const float* x = h + (size_t)row * DMODEL;

    float v[8];
    float s = 0.f, ss = 0.f;
#pragma unroll
    for (int i = 0; i < 8; i++) {
        v[i] = x[lane + i * 32];
        s  += v[i];
        ss += v[i] * v[i];
    }
#pragma unroll
    for (int off = 16; off > 0; off >>= 1) {
        s  += __shfl_xor_sync(0xffffffffu, s,  off);
        ss += __shfl_xor_sync(0xffffffffu, ss, off);
    }
    float mean = s * (1.f / DMODEL);
    float var  = ss * (1.f / DMODEL) - mean * mean;
    float rstd = rsqrtf(var + LN_EPS);

    __half* o = out + (size_t)row * DMODEL;
#pragma unroll
    for (int i = 0; i < 8; i++) {
        int cc = lane + i * 32;
        o[cc] = __float2half_rn((v[i] - mean) * rstd * w[cc] + b[cc]);
    }
}

// ---------------------------------------------------------------------------
// Causal depthwise conv (width 4) + SiLU; writes fp32 (scan) and fp16 (x_proj)
// ---------------------------------------------------------------------------
__global__ __launch_bounds__(256)
void conv_silu_kernel(const float* __restrict__ xz,
                      const float* __restrict__ cw, const float* __restrict__ cb,
                      float* __restrict__ u, __half* __restrict__ uh)
{
    int idx = blockIdx.x * blockDim.x + threadIdx.x;
    if (idx >= MROWS * DINNER) return;
    int d = idx & (DINNER - 1);
    int t = (idx >> 9) & (SEQ - 1);
    int b = idx >> 18;

    const float* base = xz + (size_t)(b * SEQ) * (2 * DINNER) + d;
    float acc = cb[d];
#pragma unroll
    for (int k = 0; k < DCONV; k++) {
        int tt = t - (DCONV - 1) + k;
        if (tt >= 0) acc += base[(size_t)tt * (2 * DINNER)] * cw[d * DCONV + k];
    }
    float uv = acc / (1.f + __expf(-acc));
    u[idx]  = uv;
    uh[idx] = __float2half_rn(uv);
}

// ---------------------------------------------------------------------------
// Selective scan v2: computes dt = softplus(dbl[:,:16] @ dtw^T + b) in-kernel
// via a second 16-lane shfl reduction; fuses +u*D, *silu(z); writes y as fp16.
// ---------------------------------------------------------------------------
__global__ __launch_bounds__(256)
void scan_kernel(const float* __restrict__ dbl, const float* __restrict__ u,
                 const float* __restrict__ xz,
                 const float* __restrict__ dtw, const float* __restrict__ dtb,
                 const float* __restrict__ A_log, const float* __restrict__ Dvec,
                 __half* __restrict__ yh)
{
    int tid  = blockIdx.x * blockDim.x + threadIdx.x;
    int s    = tid & (DSTATE - 1);
    int pair = tid >> 4;
    int d    = pair & (DINNER - 1);
    int b    = pair >> 9;

    float wts = dtw[d * DTRANK + s];
    float bia = dtb[d];
    float A   = -__expf(A_log[d * DSTATE + s]);
    float Dp  = Dvec[d];
    float h   = 0.f;

    const float* u_p  = u   + (size_t)b * SEQ * DINNER + d;
    const float* bc_p = dbl + (size_t)b * SEQ * 48;
    const float* z_p  = xz  + (size_t)b * SEQ * (2 * DINNER) + DINNER + d;
    __half*      y_p  = yh  + (size_t)b * SEQ * DINNER + d;

    for (int t = 0; t < SEQ; t++) {
        const float* row = bc_p + t * 48;
        float dtr = row[s];
        float Bv  = row[16 + s];
        float Cv  = row[32 + s];

        // dt dot product across the 16 state lanes
        float dot = dtr * wts;
        dot += __shfl_xor_sync(0xffffffffu, dot, 8);
        dot += __shfl_xor_sync(0xffffffffu, dot, 4);
        dot += __shfl_xor_sync(0xffffffffu, dot, 2);
        dot += __shfl_xor_sync(0xffffffffu, dot, 1);
        float pre = dot + bia;
        float dt  = (pre > 20.f) ? pre : log1pf(__expf(pre));

        float uv = u_p[(size_t)t * DINNER];
        h = __expf(dt * A) * h + dt * uv * Bv;
        float yv = h * Cv;
        yv += __shfl_xor_sync(0xffffffffu, yv, 8);
        yv += __shfl_xor_sync(0xffffffffu, yv, 4);
        yv += __shfl_xor_sync(0xffffffffu, yv, 2);
        yv += __shfl_xor_sync(0xffffffffu, yv, 1);

        if (s == 0) {
            float zv  = z_p[(size_t)t * (2 * DINNER)];
            float out = (yv + uv * Dp) * (zv / (1.f + __expf(-zv)));
            y_p[(size_t)t * DINNER] = __float2half_rn(out);
        }
    }
}

// ---------------------------------------------------------------------------
// Head
// ---------------------------------------------------------------------------
__global__ __launch_bounds__(256)
void head1_kernel(const float* __restrict__ h,
                  const float* __restrict__ w1, const float* __restrict__ b1,
                  float* __restrict__ t1)
{
    __shared__ float hs[DMODEL];
    int b = blockIdx.x;
    int n = threadIdx.x;
    hs[n] = h[((size_t)b * SEQ + (SEQ - 1)) * DMODEL + n];
    __syncthreads();

    const float4* wp = (const float4*)(w1 + (size_t)n * DMODEL);
    float acc = b1[n];
#pragma unroll 8
    for (int k = 0; k < DMODEL / 4; k++) {
        float4 w4 = wp[k];
        acc += hs[4*k+0]*w4.x + hs[4*k+1]*w4.y + hs[4*k+2]*w4.z + hs[4*k+3]*w4.w;
    }
    t1[b * DMODEL + n] = fmaxf(acc, 0.f);
}

__global__ __launch_bounds__(32)
void head2_kernel(const float* __restrict__ t1,
                  const float* __restrict__ w2, const float* __restrict__ b2,
                  float* __restrict__ out)
{
    int b = blockIdx.x;
    int lane = threadIdx.x;
    float acc = 0.f;
#pragma unroll
    for (int k = lane; k < DMODEL; k += 32)
        acc += t1[b * DMODEL + k] * w2[k];
#pragma unroll
    for (int off = 16; off > 0; off >>= 1)
        acc += __shfl_xor_sync(0xffffffffu, acc, off);
    if (lane == 0) out[b] = acc + b2[0];
}

// ---------------------------------------------------------------------------
// Host launcher
// ---------------------------------------------------------------------------
extern "C" void kernel_launch(void* const* d_in, const int* in_sizes, int n_in,
                              void* d_out, int out_size)
{
    const float* x            = (const float*)d_in[0];
    const float* input_proj_w = (const float*)d_in[1];
    const float* input_proj_b = (const float*)d_in[2];
    const float* ln_w         = (const float*)d_in[3];
    const float* ln_b         = (const float*)d_in[4];
    const float* in_proj_w    = (const float*)d_in[5];
    const float* conv_w       = (const float*)d_in[6];
    const float* conv_b       = (const float*)d_in[7];
    const float* x_proj_w     = (const float*)d_in[8];
    const float* dt_proj_w    = (const float*)d_in[9];
    const float* dt_proj_b    = (const float*)d_in[10];
    const float* A_log        = (const float*)d_in[11];
    const float* Dvec         = (const float*)d_in[12];
    const float* out_proj_w   = (const float*)d_in[13];
    const float* head_w1      = (const float*)d_in[14];
    const float* head_b1      = (const float*)d_in[15];
    const float* head_w2      = (const float*)d_in[16];
    const float* head_b2      = (const float*)d_in[17];
    float* out = (float*)d_out;

    float  *p_h, *p_xz, *p_u, *p_dbl, *p_t1, *p_part;
    __half *p_xnh, *p_uh, *p_yh, *p_wh;
    cudaGetSymbolAddress((void**)&p_h,    g_h);
    cudaGetSymbolAddress((void**)&p_xnh,  g_xnh);
    cudaGetSymbolAddress((void**)&p_xz,   g_xz);
    cudaGetSymbolAddress((void**)&p_u,    g_u);
    cudaGetSymbolAddress((void**)&p_uh,   g_uh);
    cudaGetSymbolAddress((void**)&p_dbl,  g_dbl);
    cudaGetSymbolAddress((void**)&p_yh,   g_yh);
    cudaGetSymbolAddress((void**)&p_t1,   g_t1);
    cudaGetSymbolAddress((void**)&p_part, g_part);
    cudaGetSymbolAddress((void**)&p_wh,   g_wh);

    // convert inputs/weights to fp16 scratch
    cvt_kernel<<< 64, 256>>>(x,            p_wh + X_H,   MROWS * INPUT_DIM);
    cvt_kernel<<<  4, 256>>>(input_proj_w, p_wh + IPW_H, DMODEL * INPUT_DIM);
    cvt_kernel<<<512, 256>>>(in_proj_w,    p_wh + INW_H, NLAYERS * 2 * DINNER * DMODEL);
    cvt_kernel<<< 48, 256>>>(x_proj_w,     p_wh + XPW_H, NLAYERS * 48 * DINNER);
    cvt_kernel<<<256, 256>>>(out_proj_w,   p_wh + OPW_H, NLAYERS * DMODEL * DINNER);

    // input projection: h = x @ W^T + b  (N=256, K=32) grid (2,32)
    gemm_h<<<dim3(DMODEL/BN, MROWS/BM, 1), 256>>>(
        p_wh + X_H, INPUT_DIM, p_wh + IPW_H, INPUT_DIM, input_proj_b,
        p_h, DMODEL, 0, DMODEL, INPUT_DIM);

    for (int l = 0; l < NLAYERS; l++) {
        // 1. layernorm -> fp16
        ln_kernel<<<MROWS / 8, 256>>>(p_h, ln_w + l * DMODEL, ln_b + l * DMODEL, p_xnh);

        // 2. in_proj: xz = xn @ W^T  (N=1024, K=256) grid (8,32) = 256 CTAs
        gemm_h<<<dim3((2*DINNER)/BN, MROWS/BM, 1), 256>>>(
            p_xnh, DMODEL, p_wh + INW_H + (size_t)l * 2 * DINNER * DMODEL, DMODEL,
            nullptr, p_xz, 2 * DINNER, 0, 2 * DINNER, DMODEL);

        // 3. conv + silu -> u (fp32 + fp16)
        conv_silu_kernel<<<(MROWS * DINNER) / 256, 256>>>(
            p_xz, conv_w + l * DINNER * DCONV, conv_b + l * DINNER, p_u, p_uh);

        // 4. x_proj: dbl = u @ W^T  (N=48, K=512), split-K=4 -> 128 CTAs
        gemm_h<<<dim3(1, MROWS/BM, 4), 256>>>(
            p_uh, DINNER, p_wh + XPW_H + (size_t)l * 48 * DINNER, DINNER,
            nullptr, p_part, 48, (size_t)MROWS * 48, 48, DINNER / 4);
        reduce_kernel<<<(MROWS * 48) / 1024, 256>>>(
            p_part, (size_t)MROWS * 48, 4, nullptr, p_dbl, MROWS * 48);

        // 5. selective scan (dt computed in-kernel; writes y fp16)
        scan_kernel<<<(MROWS * DSTATE) / 256, 256>>>(
            p_dbl, p_u, p_xz,
            dt_proj_w + (size_t)l * DINNER * DTRANK, dt_proj_b + l * DINNER,
            A_log + (size_t)l * DINNER * DSTATE, Dvec + l * DINNER, p_yh);

        // 6. out_proj: h += y @ W^T  (N=256, K=512), split-K=2, resid in reduce
        gemm_h<<<dim3(DMODEL/BN, MROWS/BM, 2), 256>>>(
            p_yh, DINNER, p_wh + OPW_H + (size_t)l * DMODEL * DINNER, DINNER,
            nullptr, p_part, DMODEL, (size_t)MROWS * DMODEL, DMODEL, DINNER / 2);
        reduce_kernel<<<(MROWS * DMODEL) / 1024, 256>>>(
            p_part, (size_t)MROWS * DMODEL, 2, p_h, p_h, MROWS * DMODEL);
    }

    // head
    head1_kernel<<<BATCH, DMODEL>>>(p_h, head_w1, head_b1, p_t1);
    head2_kernel<<<BATCH, 32>>>(p_t1, head_w2, head_b2, out);
}

// round 9
// speedup vs baseline: 1.1367x; 1.1367x over previous
#include <cuda_runtime.h>
#include <cuda_fp16.h>
#include <cstdint>

// ---------------------------------------------------------------------------
// Model constants
// ---------------------------------------------------------------------------
#define BATCH     8
#define SEQ       512
#define INPUT_DIM 32
#define DMODEL    256
#define NLAYERS   4
#define DSTATE    16
#define DCONV     4
#define DINNER    512
#define DTRANK    16
#define MROWS     (BATCH*SEQ)    // 4096
#define LN_EPS    1e-5f

// ---------------------------------------------------------------------------
// Device scratch
// ---------------------------------------------------------------------------
__device__ float  g_h   [MROWS * DMODEL];
__device__ __half g_xnh [MROWS * DMODEL];
__device__ float  g_xz  [MROWS * 2 * DINNER];
__device__ float  g_u   [MROWS * DINNER];
__device__ __half g_uh  [MROWS * DINNER];
__device__ float  g_dbl [MROWS * 48];
__device__ float  g_dt  [MROWS * DINNER];
__device__ __half g_yh  [MROWS * DINNER];
__device__ float  g_t1  [BATCH * DMODEL];
__device__ float  g_part[2 * MROWS * DMODEL];     // split-K partials

// half scratch for converted inputs/weights (offsets in halves)
#define X_H    0          // x:            131072
#define IPW_H  131072     // input_proj_w: 8192
#define INW_H  139264     // in_proj_w:    1048576 (l*262144)
#define XPW_H  1187840    // x_proj_w:     98304   (l*24576)
#define OPW_H  1286144    // out_proj_w:   524288  (l*131072)
#define WH_TOTAL 1810432
__device__ __half g_wh[WH_TOTAL];

// ---------------------------------------------------------------------------
// PTX helpers
// ---------------------------------------------------------------------------
__device__ __forceinline__ void mma_f16(float* cc, const uint32_t* a, const uint32_t* b) {
    asm volatile("mma.sync.aligned.m16n8k16.row.col.f32.f16.f16.f32 "
                 "{%0,%1,%2,%3}, {%4,%5,%6,%7}, {%8,%9}, {%0,%1,%2,%3};"
                 : "+f"(cc[0]), "+f"(cc[1]), "+f"(cc[2]), "+f"(cc[3])
                 : "r"(a[0]), "r"(a[1]), "r"(a[2]), "r"(a[3]),
                   "r"(b[0]), "r"(b[1]));
}

__device__ __forceinline__ uint32_t smem_u32(const void* p) {
    uint32_t a;
    asm("{ .reg .u64 t; cvta.to.shared.u64 t, %1; cvt.u32.u64 %0, t; }"
        : "=r"(a) : "l"(p));
    return a;
}

__device__ __forceinline__ void cpasync16(uint32_t dst, const void* src, int src_sz) {
    asm volatile("cp.async.cg.shared.global [%0], [%1], 16, %2;"
                 :: "r"(dst), "l"(src), "r"(src_sz) : "memory");
}
#define CP_COMMIT()  asm volatile("cp.async.commit_group;" ::: "memory")
#define CP_WAIT(n)   asm volatile("cp.async.wait_group %0;" :: "n"(n) : "memory")

// ---------------------------------------------------------------------------
// fp16 mma.sync NT GEMM, BK=32, cp.async double buffer (40KB static SMEM).
//   C[m,n] = sum_k A[m,k] * W[n,k]   (+bias)   fp32 accumulate/output
// CTA 128x128, 256 threads (8 warps, warp tile 32x64), 2 m16n8k16 ksteps/tile.
// Stage: A/B 128 rows x 40 halves (80B rows, conflict-free frag loads).
// Split-K via blockIdx.z. Requirements: M%128==0, Klen%32==0, lda/ldw%8==0.
// ---------------------------------------------------------------------------
#define BM 128
#define BN 128
#define BKH 32
#define SLDH 40
#define STAGE_H (BM * SLDH)    // 5120 halves

__global__ __launch_bounds__(256)
void gemm_h(const __half* __restrict__ A, int lda,
            const __half* __restrict__ W, int ldw,
            const float* __restrict__ bias,
            float* __restrict__ C, int ldc, size_t zstride,
            int N, int Klen)
{
    __shared__ __half Asm[2][STAGE_H];
    __shared__ __half Bsm[2][STAGE_H];

    const int tid  = threadIdx.x;
    const int wid  = tid >> 5;
    const int lane = tid & 31;
    const int wm   = wid & 3;
    const int wn   = wid >> 2;
    const int g    = lane >> 2;
    const int c    = lane & 3;
    const int m0   = wm * 32;
    const int n0   = wn * 64;

    const int row0 = blockIdx.y * BM;
    const int col0 = blockIdx.x * BN;
    const int kofs = blockIdx.z * Klen;
    C += (size_t)blockIdx.z * zstride;

    // cp.async: 256 threads = 128 rows x 2 half-rows of 32B (16 halves)
    const int cr = tid >> 1;
    const int ck = (tid & 1) * 16;
    const int bvalid = (col0 + cr) < N ? 16 : 0;

    const uint32_t smA = smem_u32(Asm);
    const uint32_t smB = smem_u32(Bsm);
    const int T = Klen / BKH;

    auto issue = [&](int t) {
        if (t < T) {
            const __half* Ap = A + (size_t)(row0 + cr) * lda + kofs + t * BKH + ck;
            uint32_t da = smA + ((t & 1) * STAGE_H + cr * SLDH + ck) * 2;
            cpasync16(da,      Ap,     16);
            cpasync16(da + 16, Ap + 8, 16);
            const __half* Wp = W + (size_t)(col0 + cr) * ldw + kofs + t * BKH + ck;
            uint32_t db = smB + ((t & 1) * STAGE_H + cr * SLDH + ck) * 2;
            cpasync16(db,      Wp,     bvalid);
            cpasync16(db + 16, Wp + 8, bvalid);
        }
    };

    issue(0); CP_COMMIT();

    float acc[2][8][4];
#pragma unroll
    for (int mi = 0; mi < 2; mi++)
#pragma unroll
        for (int ni = 0; ni < 8; ni++)
#pragma unroll
            for (int e = 0; e < 4; e++) acc[mi][ni][e] = 0.f;

    for (int t = 0; t < T; t++) {
        issue(t + 1);
        CP_COMMIT();
        CP_WAIT(1);
        __syncthreads();

        const __half* As = Asm[t & 1];
        const __half* Bs = Bsm[t & 1];

#pragma unroll
        for (int ks = 0; ks < 2; ks++) {
            const int kb = ks * 16;
            uint32_t a[2][4], b[8][2];
#pragma unroll
            for (int mi = 0; mi < 2; mi++) {
                const int r = m0 + mi * 16 + g;
                a[mi][0] = *(const uint32_t*)&As[(r    ) * SLDH + kb + 2 * c];
                a[mi][1] = *(const uint32_t*)&As[(r + 8) * SLDH + kb + 2 * c];
                a[mi][2] = *(const uint32_t*)&As[(r    ) * SLDH + kb + 2 * c + 8];
                a[mi][3] = *(const uint32_t*)&As[(r + 8) * SLDH + kb + 2 * c + 8];
            }
#pragma unroll
            for (int ni = 0; ni < 8; ni++) {
                const int r = n0 + ni * 8 + g;
                b[ni][0] = *(const uint32_t*)&Bs[r * SLDH + kb + 2 * c];
                b[ni][1] = *(const uint32_t*)&Bs[r * SLDH + kb + 2 * c + 8];
            }
#pragma unroll
            for (int mi = 0; mi < 2; mi++)
#pragma unroll
                for (int ni = 0; ni < 8; ni++)
                    mma_f16(acc[mi][ni], a[mi], b[ni]);
        }
        __syncthreads();
    }

    // ---- epilogue ----
#pragma unroll
    for (int mi = 0; mi < 2; mi++) {
#pragma unroll
        for (int ni = 0; ni < 8; ni++) {
            const int colb = col0 + n0 + ni * 8;
            if (colb < N) {
                const int cc = colb + c * 2;
#pragma unroll
                for (int half = 0; half < 2; half++) {
                    const int r = row0 + m0 + mi * 16 + g + half * 8;
                    float2 v = make_float2(acc[mi][ni][half * 2],
                                           acc[mi][ni][half * 2 + 1]);
                    if (bias) { v.x += bias[cc]; v.y += bias[cc + 1]; }
                    *(float2*)(C + (size_t)r * ldc + cc) = v;
                }
            }
        }
    }
}

// ---------------------------------------------------------------------------
// Merged fp32->fp16 conversion of all inputs/weights into g_wh
// ---------------------------------------------------------------------------
__global__ __launch_bounds__(256)
void cvt_all(const float* __restrict__ x,   const float* __restrict__ ipw,
             const float* __restrict__ inw, const float* __restrict__ xpw,
             const float* __restrict__ opw, __half* __restrict__ dst)
{
    int i = (blockIdx.x * blockDim.x + threadIdx.x) * 8;
    if (i >= WH_TOTAL) return;
    const float* src;
    int off;
    if      (i < IPW_H) { src = x;   off = i - X_H;   }
    else if (i < INW_H) { src = ipw; off = i - IPW_H; }
    else if (i < XPW_H) { src = inw; off = i - INW_H; }
    else if (i < OPW_H) { src = xpw; off = i - XPW_H; }
    else                { src = opw; off = i - OPW_H; }
    float4 v0 = *(const float4*)(src + off);
    float4 v1 = *(const float4*)(src + off + 4);
    __half2* d2 = (__half2*)(dst + i);
    d2[0] = __floats2half2_rn(v0.x, v0.y);
    d2[1] = __floats2half2_rn(v0.z, v0.w);
    d2[2] = __floats2half2_rn(v1.x, v1.y);
    d2[3] = __floats2half2_rn(v1.z, v1.w);
}

// ---------------------------------------------------------------------------
// Fused: h = resid + sum_z part  (row of 256), then LayerNorm -> fp16 xn.
// Block per row, 256 threads. nz may be 0 (pure LN of resid).
// ---------------------------------------------------------------------------
__global__ __launch_bounds__(256)
void reduce_ln_kernel(const float* __restrict__ part, size_t zstride, int nz,
                      const float* __restrict__ resid,
                      const float* __restrict__ w, const float* __restrict__ b,
                      float* __restrict__ h, __half* __restrict__ xnh)
{
    __shared__ float red_s[8], red_ss[8];
    const int r = blockIdx.x;
    const int t = threadIdx.x;
    const size_t idx = (size_t)r * DMODEL + t;

    float v = resid[idx];
    for (int z = 0; z < nz; z++) v += part[(size_t)z * zstride + idx];
    h[idx] = v;

    float s = v, ss = v * v;
#pragma unroll
    for (int off = 16; off > 0; off >>= 1) {
        s  += __shfl_xor_sync(0xffffffffu, s,  off);
        ss += __shfl_xor_sync(0xffffffffu, ss, off);
    }
    const int wid = t >> 5;
    if ((t & 31) == 0) { red_s[wid] = s; red_ss[wid] = ss; }
    __syncthreads();
    if (t < 8) { s = red_s[t]; ss = red_ss[t]; }
    else       { s = 0.f; ss = 0.f; }
    if (t < 32) {
#pragma unroll
        for (int off = 4; off > 0; off >>= 1) {
            s  += __shfl_xor_sync(0xffffffffu, s,  off);
            ss += __shfl_xor_sync(0xffffffffu, ss, off);
        }
        if (t == 0) { red_s[0] = s; red_ss[0] = ss; }
    }
    __syncthreads();
    float mean = red_s[0] * (1.f / DMODEL);
    float var  = red_ss[0] * (1.f / DMODEL) - mean * mean;
    float rstd = rsqrtf(var + LN_EPS);
    xnh[idx] = __float2half_rn((v - mean) * rstd * w[t] + b[t]);
}

// ---------------------------------------------------------------------------
// Fused: dbl row = sum of 4 split-K partials; dt = softplus(dbl[:16]@dtw^T+b).
// Block per row (4096), 128 threads.
// ---------------------------------------------------------------------------
__global__ __launch_bounds__(128)
void reduce_dt_kernel(const float* __restrict__ part, size_t zstride,
                      const float* __restrict__ dtw, const float* __restrict__ dtb,
                      float* __restrict__ dbl, float* __restrict__ dt)
{
    __shared__ float bc[48];
    const int r = blockIdx.x;
    const int t = threadIdx.x;

    if (t < 48) {
        const size_t idx = (size_t)r * 48 + t;
        float v = part[idx] + part[zstride + idx]
                + part[2 * zstride + idx] + part[3 * zstride + idx];
        bc[t] = v;
        dbl[idx] = v;
    }
    __syncthreads();

#pragma unroll
    for (int dd = 0; dd < 4; dd++) {
        const int d = t + dd * 128;
        const float4* wp = (const float4*)(dtw + d * DTRANK);
        float acc = dtb[d];
#pragma unroll
        for (int q = 0; q < 4; q++) {
            float4 w4 = wp[q];
            acc += bc[4*q+0]*w4.x + bc[4*q+1]*w4.y + bc[4*q+2]*w4.z + bc[4*q+3]*w4.w;
        }
        dt[(size_t)r * DINNER + d] = (acc > 20.f) ? acc : log1pf(__expf(acc));
    }
}

// ---------------------------------------------------------------------------
// Causal depthwise conv (width 4) + SiLU; writes fp32 (scan) + fp16 (x_proj)
// ---------------------------------------------------------------------------
__global__ __launch_bounds__(256)
void conv_silu_kernel(const float* __restrict__ xz,
                      const float* __restrict__ cw, const float* __restrict__ cb,
                      float* __restrict__ u, __half* __restrict__ uh)
{
    int idx = blockIdx.x * blockDim.x + threadIdx.x;
    if (idx >= MROWS * DINNER) return;
    int d = idx & (DINNER - 1);
    int t = (idx >> 9) & (SEQ - 1);
    int b = idx >> 18;

    const float* base = xz + (size_t)(b * SEQ) * (2 * DINNER) + d;
    float acc = cb[d];
#pragma unroll
    for (int k = 0; k < DCONV; k++) {
        int tt = t - (DCONV - 1) + k;
        if (tt >= 0) acc += base[(size_t)tt * (2 * DINNER)] * cw[d * DCONV + k];
    }
    float uv = acc / (1.f + __expf(-acc));
    u[idx]  = uv;
    uh[idx] = __float2half_rn(uv);
}

// ---------------------------------------------------------------------------
// Selective scan (R7 form): dt precomputed; fuses +u*D, *silu(z); y -> fp16.
// ---------------------------------------------------------------------------
__global__ __launch_bounds__(256)
void scan_kernel(const float* __restrict__ dt, const float* __restrict__ u,
                 const float* __restrict__ dbl, const float* __restrict__ xz,
                 const float* __restrict__ A_log, const float* __restrict__ Dvec,
                 __half* __restrict__ yh)
{
    int tid  = blockIdx.x * blockDim.x + threadIdx.x;
    int s    = tid & (DSTATE - 1);
    int pair = tid >> 4;
    int d    = pair & (DINNER - 1);
    int b    = pair >> 9;

    float A  = -__expf(A_log[d * DSTATE + s]);
    float Dp = Dvec[d];
    float h  = 0.f;

    const float* dt_p = dt  + (size_t)b * SEQ * DINNER + d;
    const float* u_p  = u   + (size_t)b * SEQ * DINNER + d;
    const float* bc_p = dbl + (size_t)b * SEQ * 48;
    const float* z_p  = xz  + (size_t)b * SEQ * (2 * DINNER) + DINNER + d;
    __half*      y_p  = yh  + (size_t)b * SEQ * DINNER + d;

    for (int t = 0; t < SEQ; t++) {
        float dtv = dt_p[(size_t)t * DINNER];
        float uv  = u_p [(size_t)t * DINNER];
        float Bv  = bc_p[t * 48 + DTRANK + s];
        float Cv  = bc_p[t * 48 + DTRANK + DSTATE + s];

        h = __expf(dtv * A) * h + dtv * uv * Bv;
        float yv = h * Cv;
        yv += __shfl_xor_sync(0xffffffffu, yv, 8);
        yv += __shfl_xor_sync(0xffffffffu, yv, 4);
        yv += __shfl_xor_sync(0xffffffffu, yv, 2);
        yv += __shfl_xor_sync(0xffffffffu, yv, 1);

        if (s == 0) {
            float zv  = z_p[(size_t)t * (2 * DINNER)];
            float out = (yv + uv * Dp) * (zv / (1.f + __expf(-zv)));
            y_p[(size_t)t * DINNER] = __float2half_rn(out);
        }
    }
}

// ---------------------------------------------------------------------------
// Head
// ---------------------------------------------------------------------------
__global__ __launch_bounds__(256)
void head1_kernel(const float* __restrict__ h,
                  const float* __restrict__ w1, const float* __restrict__ b1,
                  float* __restrict__ t1)
{
    __shared__ float hs[DMODEL];
    int b = blockIdx.x;
    int n = threadIdx.x;
    hs[n] = h[((size_t)b * SEQ + (SEQ - 1)) * DMODEL + n];
    __syncthreads();

    const float4* wp = (const float4*)(w1 + (size_t)n * DMODEL);
    float acc = b1[n];
#pragma unroll 8
    for (int k = 0; k < DMODEL / 4; k++) {
        float4 w4 = wp[k];
        acc += hs[4*k+0]*w4.x + hs[4*k+1]*w4.y + hs[4*k+2]*w4.z + hs[4*k+3]*w4.w;
    }
    t1[b * DMODEL + n] = fmaxf(acc, 0.f);
}

__global__ __launch_bounds__(32)
void head2_kernel(const float* __restrict__ t1,
                  const float* __restrict__ w2, const float* __restrict__ b2,
                  float* __restrict__ out)
{
    int b = blockIdx.x;
    int lane = threadIdx.x;
    float acc = 0.f;
#pragma unroll
    for (int k = lane; k < DMODEL; k += 32)
        acc += t1[b * DMODEL + k] * w2[k];
#pragma unroll
    for (int off = 16; off > 0; off >>= 1)
        acc += __shfl_xor_sync(0xffffffffu, acc, off);
    if (lane == 0) out[b] = acc + b2[0];
}

// ---------------------------------------------------------------------------
// Host launcher
// ---------------------------------------------------------------------------
extern "C" void kernel_launch(void* const* d_in, const int* in_sizes, int n_in,
                              void* d_out, int out_size)
{
    const float* x            = (const float*)d_in[0];
    const float* input_proj_w = (const float*)d_in[1];
    const float* input_proj_b = (const float*)d_in[2];
    const float* ln_w         = (const float*)d_in[3];
    const float* ln_b         = (const float*)d_in[4];
    const float* in_proj_w    = (const float*)d_in[5];
    const float* conv_w       = (const float*)d_in[6];
    const float* conv_b       = (const float*)d_in[7];
    const float* x_proj_w     = (const float*)d_in[8];
    const float* dt_proj_w    = (const float*)d_in[9];
    const float* dt_proj_b    = (const float*)d_in[10];
    const float* A_log        = (const float*)d_in[11];
    const float* Dvec         = (const float*)d_in[12];
    const float* out_proj_w   = (const float*)d_in[13];
    const float* head_w1      = (const float*)d_in[14];
    const float* head_b1      = (const float*)d_in[15];
    const float* head_w2      = (const float*)d_in[16];
    const float* head_b2      = (const float*)d_in[17];
    float* out = (float*)d_out;

    float  *p_h, *p_xz, *p_u, *p_dbl, *p_dt, *p_t1, *p_part;
    __half *p_xnh, *p_uh, *p_yh, *p_wh;
    cudaGetSymbolAddress((void**)&p_h,    g_h);
    cudaGetSymbolAddress((void**)&p_xnh,  g_xnh);
    cudaGetSymbolAddress((void**)&p_xz,   g_xz);
    cudaGetSymbolAddress((void**)&p_u,    g_u);
    cudaGetSymbolAddress((void**)&p_uh,   g_uh);
    cudaGetSymbolAddress((void**)&p_dbl,  g_dbl);
    cudaGetSymbolAddress((void**)&p_dt,   g_dt);
    cudaGetSymbolAddress((void**)&p_yh,   g_yh);
    cudaGetSymbolAddress((void**)&p_t1,   g_t1);
    cudaGetSymbolAddress((void**)&p_part, g_part);
    cudaGetSymbolAddress((void**)&p_wh,   g_wh);

    // #1: convert all fp32 operands to fp16 scratch (one launch)
    cvt_all<<<(WH_TOTAL / 8 + 255) / 256, 256>>>(
        x, input_proj_w, in_proj_w, x_proj_w, out_proj_w, p_wh);

    // #2: input projection  (N=256, K=32)
    gemm_h<<<dim3(DMODEL/BN, MROWS/BM, 1), 256>>>(
        p_wh + X_H, INPUT_DIM, p_wh + IPW_H, INPUT_DIM, input_proj_b,
        p_h, DMODEL, 0, DMODEL, INPUT_DIM);

    // #3: LN of initial h (nz=0)
    reduce_ln_kernel<<<MROWS, 256>>>(nullptr, 0, 0, p_h,
                                     ln_w, ln_b, p_h, p_xnh);

    for (int l = 0; l < NLAYERS; l++) {
        // #4 (l=0): in_proj  (N=1024, K=256) grid (8,32)
        gemm_h<<<dim3((2*DINNER)/BN, MROWS/BM, 1), 256>>>(
            p_xnh, DMODEL, p_wh + INW_H + (size_t)l * 2 * DINNER * DMODEL, DMODEL,
            nullptr, p_xz, 2 * DINNER, 0, 2 * DINNER, DMODEL);

        // conv + silu
        conv_silu_kernel<<<(MROWS * DINNER) / 256, 256>>>(
            p_xz, conv_w + l * DINNER * DCONV, conv_b + l * DINNER, p_u, p_uh);

        // x_proj (N=48, K=512) split-K=4
        gemm_h<<<dim3(1, MROWS/BM, 4), 256>>>(
            p_uh, DINNER, p_wh + XPW_H + (size_t)l * 48 * DINNER, DINNER,
            nullptr, p_part, 48, (size_t)MROWS * 48, 48, DINNER / 4);

        // fused split-K reduce + dt projection + softplus
        reduce_dt_kernel<<<MROWS, 128>>>(
            p_part, (size_t)MROWS * 48,
            dt_proj_w + (size_t)l * DINNER * DTRANK, dt_proj_b + l * DINNER,
            p_dbl, p_dt);

        // selective scan
        scan_kernel<<<(MROWS * DSTATE) / 256, 256>>>(
            p_dt, p_u, p_dbl, p_xz,
            A_log + (size_t)l * DINNER * DSTATE, Dvec + l * DINNER, p_yh);

        // out_proj (N=256, K=512) split-K=2
        gemm_h<<<dim3(DMODEL/BN, MROWS/BM, 2), 256>>>(
            p_yh, DINNER, p_wh + OPW_H + (size_t)l * DMODEL * DINNER, DINNER,
            nullptr, p_part, DMODEL, (size_t)MROWS * DMODEL, DMODEL, DINNER / 2);

        // fused residual reduce + LN (next layer's xn; harmless on last layer)
        reduce_ln_kernel<<<MROWS, 256>>>(
            p_part, (size_t)MROWS * DMODEL, 2, p_h,
            ln_w + ((l + 1 < NLAYERS) ? (l + 1) : l) * DMODEL,
            ln_b + ((l + 1 < NLAYERS) ? (l + 1) : l) * DMODEL,
            p_h, p_xnh);
    }

    // head
    head1_kernel<<<BATCH, DMODEL>>>(p_h, head_w1, head_b1, p_t1);
    head2_kernel<<<BATCH, 32>>>(p_t1, head_w2, head_b2, out);
}

// round 10
// speedup vs baseline: 2.3828x; 2.0962x over previous
#include <cuda_runtime.h>
#include <cuda_fp16.h>
#include <cstdint>

// ---------------------------------------------------------------------------
// Model constants
// ---------------------------------------------------------------------------
#define BATCH     8
#define SEQ       512
#define INPUT_DIM 32
#define DMODEL    256
#define NLAYERS   4
#define DSTATE    16
#define DCONV     4
#define DINNER    512
#define DTRANK    16
#define MROWS     (BATCH*SEQ)    // 4096
#define LN_EPS    1e-5f

// ---------------------------------------------------------------------------
// Device scratch
// ---------------------------------------------------------------------------
__device__ float  g_h   [MROWS * DMODEL];
__device__ __half g_xnh [MROWS * DMODEL];
__device__ float  g_xz  [MROWS * 2 * DINNER];
__device__ float  g_u   [MROWS * DINNER];
__device__ __half g_uh  [MROWS * DINNER];
__device__ float  g_dbl [MROWS * 48];
__device__ float  g_dt  [MROWS * DINNER];
__device__ __half g_yh  [MROWS * DINNER];
__device__ float  g_t1  [BATCH * DMODEL];
__device__ float  g_part[2 * MROWS * DMODEL];     // split-K partials

// half scratch for converted inputs/weights (offsets in halves)
#define X_H    0          // x:            131072
#define IPW_H  131072     // input_proj_w: 8192
#define INW_H  139264     // in_proj_w:    1048576 (l*262144)
#define XPW_H  1187840    // x_proj_w:     98304   (l*24576)
#define OPW_H  1286144    // out_proj_w:   524288  (l*131072)
#define WH_TOTAL 1810432
__device__ __half g_wh[WH_TOTAL];

// ---------------------------------------------------------------------------
// PTX helpers
// ---------------------------------------------------------------------------
__device__ __forceinline__ void mma_f16(float* cc, const uint32_t* a, const uint32_t* b) {
    asm volatile("mma.sync.aligned.m16n8k16.row.col.f32.f16.f16.f32 "
                 "{%0,%1,%2,%3}, {%4,%5,%6,%7}, {%8,%9}, {%0,%1,%2,%3};"
                 : "+f"(cc[0]), "+f"(cc[1]), "+f"(cc[2]), "+f"(cc[3])
                 : "r"(a[0]), "r"(a[1]), "r"(a[2]), "r"(a[3]),
                   "r"(b[0]), "r"(b[1]));
}

__device__ __forceinline__ uint32_t smem_u32(const void* p) {
    uint32_t a;
    asm("{ .reg .u64 t; cvta.to.shared.u64 t, %1; cvt.u32.u64 %0, t; }"
        : "=r"(a) : "l"(p));
    return a;
}

__device__ __forceinline__ void cpasync16(uint32_t dst, const void* src, int src_sz) {
    asm volatile("cp.async.cg.shared.global [%0], [%1], 16, %2;"
                 :: "r"(dst), "l"(src), "r"(src_sz) : "memory");
}
#define CP_COMMIT()  asm volatile("cp.async.commit_group;" ::: "memory")
#define CP_WAIT(n)   asm volatile("cp.async.wait_group %0;" :: "n"(n) : "memory")

// ---------------------------------------------------------------------------
// fp16 mma.sync NT GEMM, BK=32, cp.async double buffer (40KB static SMEM).
// (unchanged from R9)
// ---------------------------------------------------------------------------
#define BM 128
#define BN 128
#define BKH 32
#define SLDH 40
#define STAGE_H (BM * SLDH)    // 5120 halves

__global__ __launch_bounds__(256)
void gemm_h(const __half* __restrict__ A, int lda,
            const __half* __restrict__ W, int ldw,
            const float* __restrict__ bias,
            float* __restrict__ C, int ldc, size_t zstride,
            int N, int Klen)
{
    __shared__ __half Asm[2][STAGE_H];
    __shared__ __half Bsm[2][STAGE_H];

    const int tid  = threadIdx.x;
    const int wid  = tid >> 5;
    const int lane = tid & 31;
    const int wm   = wid & 3;
    const int wn   = wid >> 2;
    const int g    = lane >> 2;
    const int c    = lane & 3;
    const int m0   = wm * 32;
    const int n0   = wn * 64;

    const int row0 = blockIdx.y * BM;
    const int col0 = blockIdx.x * BN;
    const int kofs = blockIdx.z * Klen;
    C += (size_t)blockIdx.z * zstride;

    const int cr = tid >> 1;
    const int ck = (tid & 1) * 16;
    const int bvalid = (col0 + cr) < N ? 16 : 0;

    const uint32_t smA = smem_u32(Asm);
    const uint32_t smB = smem_u32(Bsm);
    const int T = Klen / BKH;

    auto issue = [&](int t) {
        if (t < T) {
            const __half* Ap = A + (size_t)(row0 + cr) * lda + kofs + t * BKH + ck;
            uint32_t da = smA + ((t & 1) * STAGE_H + cr * SLDH + ck) * 2;
            cpasync16(da,      Ap,     16);
            cpasync16(da + 16, Ap + 8, 16);
            const __half* Wp = W + (size_t)(col0 + cr) * ldw + kofs + t * BKH + ck;
            uint32_t db = smB + ((t & 1) * STAGE_H + cr * SLDH + ck) * 2;
            cpasync16(db,      Wp,     bvalid);
            cpasync16(db + 16, Wp + 8, bvalid);
        }
    };

    issue(0); CP_COMMIT();

    float acc[2][8][4];
#pragma unroll
    for (int mi = 0; mi < 2; mi++)
#pragma unroll
        for (int ni = 0; ni < 8; ni++)
#pragma unroll
            for (int e = 0; e < 4; e++) acc[mi][ni][e] = 0.f;

    for (int t = 0; t < T; t++) {
        issue(t + 1);
        CP_COMMIT();
        CP_WAIT(1);
        __syncthreads();

        const __half* As = Asm[t & 1];
        const __half* Bs = Bsm[t & 1];

#pragma unroll
        for (int ks = 0; ks < 2; ks++) {
            const int kb = ks * 16;
            uint32_t a[2][4], b[8][2];
#pragma unroll
            for (int mi = 0; mi < 2; mi++) {
                const int r = m0 + mi * 16 + g;
                a[mi][0] = *(const uint32_t*)&As[(r    ) * SLDH + kb + 2 * c];
                a[mi][1] = *(const uint32_t*)&As[(r + 8) * SLDH + kb + 2 * c];
                a[mi][2] = *(const uint32_t*)&As[(r    ) * SLDH + kb + 2 * c + 8];
                a[mi][3] = *(const uint32_t*)&As[(r + 8) * SLDH + kb + 2 * c + 8];
            }
#pragma unroll
            for (int ni = 0; ni < 8; ni++) {
                const int r = n0 + ni * 8 + g;
                b[ni][0] = *(const uint32_t*)&Bs[r * SLDH + kb + 2 * c];
                b[ni][1] = *(const uint32_t*)&Bs[r * SLDH + kb + 2 * c + 8];
            }
#pragma unroll
            for (int mi = 0; mi < 2; mi++)
#pragma unroll
                for (int ni = 0; ni < 8; ni++)
                    mma_f16(acc[mi][ni], a[mi], b[ni]);
        }
        __syncthreads();
    }

#pragma unroll
    for (int mi = 0; mi < 2; mi++) {
#pragma unroll
        for (int ni = 0; ni < 8; ni++) {
            const int colb = col0 + n0 + ni * 8;
            if (colb < N) {
                const int cc = colb + c * 2;
#pragma unroll
                for (int half = 0; half < 2; half++) {
                    const int r = row0 + m0 + mi * 16 + g + half * 8;
                    float2 v = make_float2(acc[mi][ni][half * 2],
                                           acc[mi][ni][half * 2 + 1]);
                    if (bias) { v.x += bias[cc]; v.y += bias[cc + 1]; }
                    *(float2*)(C + (size_t)r * ldc + cc) = v;
                }
            }
        }
    }
}

// ---------------------------------------------------------------------------
// Merged fp32->fp16 conversion of all inputs/weights into g_wh
// ---------------------------------------------------------------------------
__global__ __launch_bounds__(256)
void cvt_all(const float* __restrict__ x,   const float* __restrict__ ipw,
             const float* __restrict__ inw, const float* __restrict__ xpw,
             const float* __restrict__ opw, __half* __restrict__ dst)
{
    int i = (blockIdx.x * blockDim.x + threadIdx.x) * 8;
    if (i >= WH_TOTAL) return;
    const float* src;
    int off;
    if      (i < IPW_H) { src = x;   off = i - X_H;   }
    else if (i < INW_H) { src = ipw; off = i - IPW_H; }
    else if (i < XPW_H) { src = inw; off = i - INW_H; }
    else if (i < OPW_H) { src = xpw; off = i - XPW_H; }
    else                { src = opw; off = i - OPW_H; }
    float4 v0 = *(const float4*)(src + off);
    float4 v1 = *(const float4*)(src + off + 4);
    __half2* d2 = (__half2*)(dst + i);
    d2[0] = __floats2half2_rn(v0.x, v0.y);
    d2[1] = __floats2half2_rn(v0.z, v0.w);
    d2[2] = __floats2half2_rn(v1.x, v1.y);
    d2[3] = __floats2half2_rn(v1.z, v1.w);
}

// ---------------------------------------------------------------------------
// Fused: h = resid + sum_z part, then LayerNorm -> fp16 xn. Block per row.
// ---------------------------------------------------------------------------
__global__ __launch_bounds__(256)
void reduce_ln_kernel(const float* __restrict__ part, size_t zstride, int nz,
                      const float* __restrict__ resid,
                      const float* __restrict__ w, const float* __restrict__ b,
                      float* __restrict__ h, __half* __restrict__ xnh)
{
    __shared__ float red_s[8], red_ss[8];
    const int r = blockIdx.x;
    const int t = threadIdx.x;
    const size_t idx = (size_t)r * DMODEL + t;

    float v = resid[idx];
    for (int z = 0; z < nz; z++) v += part[(size_t)z * zstride + idx];
    h[idx] = v;

    float s = v, ss = v * v;
#pragma unroll
    for (int off = 16; off > 0; off >>= 1) {
        s  += __shfl_xor_sync(0xffffffffu, s,  off);
        ss += __shfl_xor_sync(0xffffffffu, ss, off);
    }
    const int wid = t >> 5;
    if ((t & 31) == 0) { red_s[wid] = s; red_ss[wid] = ss; }
    __syncthreads();
    if (t < 8) { s = red_s[t]; ss = red_ss[t]; }
    else       { s = 0.f; ss = 0.f; }
    if (t < 32) {
#pragma unroll
        for (int off = 4; off > 0; off >>= 1) {
            s  += __shfl_xor_sync(0xffffffffu, s,  off);
            ss += __shfl_xor_sync(0xffffffffu, ss, off);
        }
        if (t == 0) { red_s[0] = s; red_ss[0] = ss; }
    }
    __syncthreads();
    float mean = red_s[0] * (1.f / DMODEL);
    float var  = red_ss[0] * (1.f / DMODEL) - mean * mean;
    float rstd = rsqrtf(var + LN_EPS);
    xnh[idx] = __float2half_rn((v - mean) * rstd * w[t] + b[t]);
}

// ---------------------------------------------------------------------------
// Fused: dbl row = sum of 4 split-K partials; dt = softplus(dbl[:16]@dtw^T+b)
// ---------------------------------------------------------------------------
__global__ __launch_bounds__(128)
void reduce_dt_kernel(const float* __restrict__ part, size_t zstride,
                      const float* __restrict__ dtw, const float* __restrict__ dtb,
                      float* __restrict__ dbl, float* __restrict__ dt)
{
    __shared__ float bc[48];
    const int r = blockIdx.x;
    const int t = threadIdx.x;

    if (t < 48) {
        const size_t idx = (size_t)r * 48 + t;
        float v = part[idx] + part[zstride + idx]
                + part[2 * zstride + idx] + part[3 * zstride + idx];
        bc[t] = v;
        dbl[idx] = v;
    }
    __syncthreads();

#pragma unroll
    for (int dd = 0; dd < 4; dd++) {
        const int d = t + dd * 128;
        const float4* wp = (const float4*)(dtw + d * DTRANK);
        float acc = dtb[d];
#pragma unroll
        for (int q = 0; q < 4; q++) {
            float4 w4 = wp[q];
            acc += bc[4*q+0]*w4.x + bc[4*q+1]*w4.y + bc[4*q+2]*w4.z + bc[4*q+3]*w4.w;
        }
        dt[(size_t)r * DINNER + d] = (acc > 20.f) ? acc : log1pf(__expf(acc));
    }
}

// ---------------------------------------------------------------------------
// Causal depthwise conv (width 4) + SiLU; writes fp32 (scan) + fp16 (x_proj)
// ---------------------------------------------------------------------------
__global__ __launch_bounds__(256)
void conv_silu_kernel(const float* __restrict__ xz,
                      const float* __restrict__ cw, const float* __restrict__ cb,
                      float* __restrict__ u, __half* __restrict__ uh)
{
    int idx = blockIdx.x * blockDim.x + threadIdx.x;
    if (idx >= MROWS * DINNER) return;
    int d = idx & (DINNER - 1);
    int t = (idx >> 9) & (SEQ - 1);
    int b = idx >> 18;

    const float* base = xz + (size_t)(b * SEQ) * (2 * DINNER) + d;
    float acc = cb[d];
#pragma unroll
    for (int k = 0; k < DCONV; k++) {
        int tt = t - (DCONV - 1) + k;
        if (tt >= 0) acc += base[(size_t)tt * (2 * DINNER)] * cw[d * DCONV + k];
    }
    float uv = acc / (1.f + __expf(-acc));
    u[idx]  = uv;
    uh[idx] = __float2half_rn(uv);
}

// ---------------------------------------------------------------------------
// Selective scan v3: cp.async SMEM-staged, chunked (Tc=32), double-buffered.
// Block = 16 consecutive d of one batch b (256 blocks), 256 threads:
// thread = (p, s), p = local d (0..15), s = state (0..15).
// Stage layout (floats): [0:512) dt, [512:1024) u, [1024:1536) z, [1536:3072) bc
// ---------------------------------------------------------------------------
#define TC 32
#define SSTAGE 3072

__global__ __launch_bounds__(256)
void scan_kernel(const float* __restrict__ dt, const float* __restrict__ u,
                 const float* __restrict__ dbl, const float* __restrict__ xz,
                 const float* __restrict__ A_log, const float* __restrict__ Dvec,
                 __half* __restrict__ yh)
{
    __shared__ float stage[2][SSTAGE];

    const int tid = threadIdx.x;
    const int p   = tid >> 4;            // local d
    const int s   = tid & 15;            // state
    const int b   = blockIdx.x >> 5;     // batch
    const int d0  = (blockIdx.x & 31) * 16;
    const int d   = d0 + p;

    const uint32_t smBase = smem_u32(stage);
    const size_t rowbase = (size_t)b * SEQ;

    // cp.async staging: 768 16B-ops per stage, 3 per thread
    auto load_chunk = [&](int c) {
        if (c >= SEQ / TC) return;
        const int t0 = c * TC;
        const uint32_t dst0 = smBase + (c & 1) * SSTAGE * 4;
#pragma unroll
        for (int k = 0; k < 3; k++) {
            const int o = tid + k * 256;
            const float* src;
            int soff;
            if (o < 128) {               // dt: t = o>>2, q = o&3
                const int t = o >> 2, q = o & 3;
                src  = dt + (rowbase + t0 + t) * DINNER + d0 + q * 4;
                soff = t * 16 + q * 4;
            } else if (o < 256) {        // u
                const int o2 = o - 128;
                const int t = o2 >> 2, q = o2 & 3;
                src  = u + (rowbase + t0 + t) * DINNER + d0 + q * 4;
                soff = 512 + t * 16 + q * 4;
            } else if (o < 384) {        // z (second half of xz row)
                const int o2 = o - 256;
                const int t = o2 >> 2, q = o2 & 3;
                src  = xz + (rowbase + t0 + t) * (2 * DINNER) + DINNER + d0 + q * 4;
                soff = 1024 + t * 16 + q * 4;
            } else {                     // bc: 12 chunks per t
                const int o2 = o - 384;
                const int t = o2 / 12, q = o2 % 12;
                src  = dbl + (rowbase + t0 + t) * 48 + q * 4;
                soff = 1536 + t * 48 + q * 4;
            }
            cpasync16(dst0 + soff * 4, src, 16);
        }
    };

    const float A  = -__expf(A_log[d * DSTATE + s]);
    const float Dp = Dvec[d];
    float h = 0.f;

    __half* y_p = yh + rowbase * DINNER + d;

    load_chunk(0); CP_COMMIT();

    for (int c = 0; c < SEQ / TC; c++) {
        load_chunk(c + 1);
        CP_COMMIT();
        CP_WAIT(1);
        __syncthreads();

        const float* st = stage[c & 1];
        const int t0 = c * TC;

#pragma unroll 4
        for (int tt = 0; tt < TC; tt++) {
            float dtv = st[tt * 16 + p];
            float uv  = st[512 + tt * 16 + p];
            float Bv  = st[1536 + tt * 48 + 16 + s];
            float Cv  = st[1536 + tt * 48 + 32 + s];

            h = __expf(dtv * A) * h + dtv * uv * Bv;
            float yv = h * Cv;
            yv += __shfl_xor_sync(0xffffffffu, yv, 8);
            yv += __shfl_xor_sync(0xffffffffu, yv, 4);
            yv += __shfl_xor_sync(0xffffffffu, yv, 2);
            yv += __shfl_xor_sync(0xffffffffu, yv, 1);

            if (s == 0) {
                float zv  = st[1024 + tt * 16 + p];
                float out = (yv + uv * Dp) * (zv / (1.f + __expf(-zv)));
                y_p[(size_t)(t0 + tt) * DINNER] = __float2half_rn(out);
            }
        }
        __syncthreads();
    }
}

// ---------------------------------------------------------------------------
// Head
// ---------------------------------------------------------------------------
__global__ __launch_bounds__(256)
void head1_kernel(const float* __restrict__ h,
                  const float* __restrict__ w1, const float* __restrict__ b1,
                  float* __restrict__ t1)
{
    __shared__ float hs[DMODEL];
    int b = blockIdx.x;
    int n = threadIdx.x;
    hs[n] = h[((size_t)b * SEQ + (SEQ - 1)) * DMODEL + n];
    __syncthreads();

    const float4* wp = (const float4*)(w1 + (size_t)n * DMODEL);
    float acc = b1[n];
#pragma unroll 8
    for (int k = 0; k < DMODEL / 4; k++) {
        float4 w4 = wp[k];
        acc += hs[4*k+0]*w4.x + hs[4*k+1]*w4.y + hs[4*k+2]*w4.z + hs[4*k+3]*w4.w;
    }
    t1[b * DMODEL + n] = fmaxf(acc, 0.f);
}

__global__ __launch_bounds__(32)
void head2_kernel(const float* __restrict__ t1,
                  const float* __restrict__ w2, const float* __restrict__ b2,
                  float* __restrict__ out)
{
    int b = blockIdx.x;
    int lane = threadIdx.x;
    float acc = 0.f;
#pragma unroll
    for (int k = lane; k < DMODEL; k += 32)
        acc += t1[b * DMODEL + k] * w2[k];
#pragma unroll
    for (int off = 16; off > 0; off >>= 1)
        acc += __shfl_xor_sync(0xffffffffu, acc, off);
    if (lane == 0) out[b] = acc + b2[0];
}

// ---------------------------------------------------------------------------
// Host launcher
// ---------------------------------------------------------------------------
extern "C" void kernel_launch(void* const* d_in, const int* in_sizes, int n_in,
                              void* d_out, int out_size)
{
    const float* x            = (const float*)d_in[0];
    const float* input_proj_w = (const float*)d_in[1];
    const float* input_proj_b = (const float*)d_in[2];
    const float* ln_w         = (const float*)d_in[3];
    const float* ln_b         = (const float*)d_in[4];
    const float* in_proj_w    = (const float*)d_in[5];
    const float* conv_w       = (const float*)d_in[6];
    const float* conv_b       = (const float*)d_in[7];
    const float* x_proj_w     = (const float*)d_in[8];
    const float* dt_proj_w    = (const float*)d_in[9];
    const float* dt_proj_b    = (const float*)d_in[10];
    const float* A_log        = (const float*)d_in[11];
    const float* Dvec         = (const float*)d_in[12];
    const float* out_proj_w   = (const float*)d_in[13];
    const float* head_w1      = (const float*)d_in[14];
    const float* head_b1      = (const float*)d_in[15];
    const float* head_w2      = (const float*)d_in[16];
    const float* head_b2      = (const float*)d_in[17];
    float* out = (float*)d_out;

    float  *p_h, *p_xz, *p_u, *p_dbl, *p_dt, *p_t1, *p_part;
    __half *p_xnh, *p_uh, *p_yh, *p_wh;
    cudaGetSymbolAddress((void**)&p_h,    g_h);
    cudaGetSymbolAddress((void**)&p_xnh,  g_xnh);
    cudaGetSymbolAddress((void**)&p_xz,   g_xz);
    cudaGetSymbolAddress((void**)&p_u,    g_u);
    cudaGetSymbolAddress((void**)&p_uh,   g_uh);
    cudaGetSymbolAddress((void**)&p_dbl,  g_dbl);
    cudaGetSymbolAddress((void**)&p_dt,   g_dt);
    cudaGetSymbolAddress((void**)&p_yh,   g_yh);
    cudaGetSymbolAddress((void**)&p_t1,   g_t1);
    cudaGetSymbolAddress((void**)&p_part, g_part);
    cudaGetSymbolAddress((void**)&p_wh,   g_wh);

    // convert all fp32 operands to fp16 scratch (one launch)
    cvt_all<<<(WH_TOTAL / 8 + 255) / 256, 256>>>(
        x, input_proj_w, in_proj_w, x_proj_w, out_proj_w, p_wh);

    // input projection  (N=256, K=32)
    gemm_h<<<dim3(DMODEL/BN, MROWS/BM, 1), 256>>>(
        p_wh + X_H, INPUT_DIM, p_wh + IPW_H, INPUT_DIM, input_proj_b,
        p_h, DMODEL, 0, DMODEL, INPUT_DIM);

    // LN of initial h (nz=0)
    reduce_ln_kernel<<<MROWS, 256>>>(nullptr, 0, 0, p_h,
                                     ln_w, ln_b, p_h, p_xnh);

    for (int l = 0; l < NLAYERS; l++) {
        // in_proj  (N=1024, K=256)
        gemm_h<<<dim3((2*DINNER)/BN, MROWS/BM, 1), 256>>>(
            p_xnh, DMODEL, p_wh + INW_H + (size_t)l * 2 * DINNER * DMODEL, DMODEL,
            nullptr, p_xz, 2 * DINNER, 0, 2 * DINNER, DMODEL);

        // conv + silu
        conv_silu_kernel<<<(MROWS * DINNER) / 256, 256>>>(
            p_xz, conv_w + l * DINNER * DCONV, conv_b + l * DINNER, p_u, p_uh);

        // x_proj (N=48, K=512) split-K=4
        gemm_h<<<dim3(1, MROWS/BM, 4), 256>>>(
            p_uh, DINNER, p_wh + XPW_H + (size_t)l * 48 * DINNER, DINNER,
            nullptr, p_part, 48, (size_t)MROWS * 48, 48, DINNER / 4);

        // fused split-K reduce + dt projection + softplus
        reduce_dt_kernel<<<MROWS, 128>>>(
            p_part, (size_t)MROWS * 48,
            dt_proj_w + (size_t)l * DINNER * DTRANK, dt_proj_b + l * DINNER,
            p_dbl, p_dt);

        // selective scan (SMEM-staged)
        scan_kernel<<<256, 256>>>(
            p_dt, p_u, p_dbl, p_xz,
            A_log + (size_t)l * DINNER * DSTATE, Dvec + l * DINNER, p_yh);

        // out_proj (N=256, K=512) split-K=2
        gemm_h<<<dim3(DMODEL/BN, MROWS/BM, 2), 256>>>(
            p_yh, DINNER, p_wh + OPW_H + (size_t)l * DMODEL * DINNER, DINNER,
            nullptr, p_part, DMODEL, (size_t)MROWS * DMODEL, DMODEL, DINNER / 2);

        // fused residual reduce + LN (next layer's xn; harmless on last layer)
        reduce_ln_kernel<<<MROWS, 256>>>(
            p_part, (size_t)MROWS * DMODEL, 2, p_h,
            ln_w + ((l + 1 < NLAYERS) ? (l + 1) : l) * DMODEL,
            ln_b + ((l + 1 < NLAYERS) ? (l + 1) : l) * DMODEL,
            p_h, p_xnh);
    }

    // head
    head1_kernel<<<BATCH, DMODEL>>>(p_h, head_w1, head_b1, p_t1);
    head2_kernel<<<BATCH, 32>>>(p_t1, head_w2, head_b2, out);
}